// round 12
// baseline (speedup 1.0000x reference)
#include <cuda_runtime.h>
#include <cuda_fp16.h>
#include <cstdint>

#define BB  8
#define TT  1000
#define NHH 8
#define DD  64
#define SCALE_LOG2E (-0.18033688011112042f)

__device__ __half g_qh[BB*NHH*TT*DD];
__device__ __half g_kh[BB*NHH*TT*DD];
__device__ __half g_vh[BB*NHH*TT*DD];
__device__ __half g_hoh[BB*NHH*TT*DD];

__device__ __forceinline__ __half2 habs2_(__half2 a) {
  unsigned u = (*(unsigned*)&a) & 0x7FFF7FFFu;
  return *(__half2*)&u;
}
__device__ __forceinline__ unsigned smem_u32(const void* p) {
  return (unsigned)__cvta_generic_to_shared(p);
}

// K0: k = x*wk -> fp16
__global__ __launch_bounds__(256) void kpack_kernel(
    const float* __restrict__ x, const float* __restrict__ wk) {
  __shared__ float xs[32][68];
  __shared__ float wks[512];
  const int tid = threadIdx.x, tok0 = blockIdx.x * 32;
  for (int i = tid; i < 512; i += 256) wks[i] = wk[i];
  for (int i = tid; i < 512; i += 256) {
    int tl = i >> 4, k4 = (i & 15) << 2;
    float4 v = *(const float4*)&x[(tok0 + tl)*DD + k4];
    xs[tl][k4] = v.x; xs[tl][k4+1] = v.y; xs[tl][k4+2] = v.z; xs[tl][k4+3] = v.w;
  }
  __syncthreads();
  const int h = tid >> 5, tl = tid & 31;
  const int gt = tok0 + tl, b = gt / TT, t = gt - b*TT;
  __half* dst = g_kh + ((size_t)(b*NHH + h)*TT + t)*DD;
  #pragma unroll
  for (int c = 0; c < 8; c++) {
    int d = c*8;
    __half2 h0 = __floats2half2_rn(xs[tl][d]*wks[h*64+d],     xs[tl][d+1]*wks[h*64+d+1]);
    __half2 h1 = __floats2half2_rn(xs[tl][d+2]*wks[h*64+d+2], xs[tl][d+3]*wks[h*64+d+3]);
    __half2 h2 = __floats2half2_rn(xs[tl][d+4]*wks[h*64+d+4], xs[tl][d+5]*wks[h*64+d+5]);
    __half2 h3 = __floats2half2_rn(xs[tl][d+6]*wks[h*64+d+6], xs[tl][d+7]*wks[h*64+d+7]);
    uint4 o; o.x=*(unsigned*)&h0; o.y=*(unsigned*)&h1; o.z=*(unsigned*)&h2; o.w=*(unsigned*)&h3;
    *(uint4*)(dst + d) = o;
  }
}

// K1: Q/V projection -> fp16 [b,h][t][d]
__global__ __launch_bounds__(256) void qv_kernel(
    const float* __restrict__ x, const float* __restrict__ wq,
    const float* __restrict__ wv) {
  const float* w = blockIdx.z ? wv : wq;
  __half* dstg   = blockIdx.z ? g_vh : g_qh;
  const int m0 = blockIdx.x * 64, n0 = blockIdx.y * 64;
  __shared__ float xs[64*68];
  __shared__ float ws[64*68];
  const int tid = threadIdx.x;
  for (int i = tid; i < 1024; i += 256) {
    int m = i >> 4, k4 = (i & 15) << 2;
    float4 v4 = *(const float4*)&x[(m0 + m)*DD + k4];
    xs[(k4)*68+m]=v4.x; xs[(k4+1)*68+m]=v4.y; xs[(k4+2)*68+m]=v4.z; xs[(k4+3)*68+m]=v4.w;
  }
  for (int i = tid; i < 4096; i += 256) {
    int n = i >> 6, k = i & 63;
    ws[k*68 + n] = w[(n0 + n)*65 + k];
  }
  __syncthreads();
  const int tm = (tid >> 4) * 4, tn = (tid & 15) * 4;
  float acc[4][4];
  #pragma unroll
  for (int i = 0; i < 4; i++)
    #pragma unroll
    for (int j = 0; j < 4; j++) acc[i][j] = 0.f;
  #pragma unroll 8
  for (int k = 0; k < 64; k++) {
    float4 a4 = *(const float4*)&xs[k*68 + tm];
    float4 b4 = *(const float4*)&ws[k*68 + tn];
    float av[4] = {a4.x,a4.y,a4.z,a4.w}, bv[4] = {b4.x,b4.y,b4.z,b4.w};
    #pragma unroll
    for (int i = 0; i < 4; i++)
      #pragma unroll
      for (int j = 0; j < 4; j++) acc[i][j] += av[i]*bv[j];
  }
  const int n = n0 + tn, h = n >> 6, d0 = n & 63;
  float b0=w[n*65+64], b1=w[(n+1)*65+64], b2=w[(n+2)*65+64], b3=w[(n+3)*65+64];
  #pragma unroll
  for (int i = 0; i < 4; i++) {
    int m = m0 + tm + i, b = m / TT, t = m - b*TT;
    __half2 h01 = __floats2half2_rn(acc[i][0]+b0, acc[i][1]+b1);
    __half2 h23 = __floats2half2_rn(acc[i][2]+b2, acc[i][3]+b3);
    uint2 o; o.x=*(unsigned*)&h01; o.y=*(unsigned*)&h23;
    *(uint2*)(dstg + ((size_t)(b*NHH+h)*TT + t)*DD + d0) = o;
  }
}

// K2 smem: qsh dup unsigned [64][68] @0 (17408); ksh pair-shuffled unsigned
// [64][36] @17408 (9216); vsm half [64][72] x2 @26624 (18432). tot 45056 -> occ5
#define SM_QSH   0
#define SM_KSH   17408
#define SM_VSM   26624
#define ATTN_SMEM 45056

__global__ __launch_bounds__(128, 5) void attn_kernel() {
  extern __shared__ char sm[];
  unsigned* qsh = (unsigned*)(sm + SM_QSH);
  unsigned* ksh = (unsigned*)(sm + SM_KSH);

  const int tid = threadIdx.x, wid = tid >> 5, lid = tid & 31;
  const int bh = blockIdx.z*NHH + blockIdx.y;
  const int t0 = blockIdx.x * 64;
  const int lam = lid & 3;
  const int r0 = wid*16 + (lid >> 2), r1 = r0 + 8;

  const __half* qhg = g_qh + (size_t)bh*TT*DD;
  const __half* khg = g_kh + (size_t)bh*TT*DD;
  const __half* vhg = g_vh + (size_t)bh*TT*DD;

  // q -> qsh[d][t] duplicated
  for (int i = tid; i < 1024; i += 128) {
    int t = i >> 4, c4 = (i & 15) << 2;
    int tr = t0 + t; if (tr >= TT) tr = TT - 1;
    uint2 a = *(const uint2*)(qhg + (size_t)tr*DD + c4);
    qsh[(c4)*68+t]   = __byte_perm(a.x, a.x, 0x1010);
    qsh[(c4+1)*68+t] = __byte_perm(a.x, a.x, 0x3232);
    qsh[(c4+2)*68+t] = __byte_perm(a.y, a.y, 0x1010);
    qsh[(c4+3)*68+t] = __byte_perm(a.y, a.y, 0x3232);
  }

  uint2 ka[4], kc[4];
  auto kpref = [&](int s0) {
    #pragma unroll
    for (int i = 0; i < 4; i++) {
      int idx = tid + i*128;
      int sp = idx >> 4, c4 = (idx & 15) << 2;
      int sA = s0 + 2*sp, sB = sA + 1;
      if (sA >= TT) sA = TT - 1;
      if (sB >= TT) sB = TT - 1;
      ka[i] = *(const uint2*)(khg + (size_t)sA*DD + c4);
      kc[i] = *(const uint2*)(khg + (size_t)sB*DD + c4);
    }
  };
  // pair p stored at column j = 8*(p&3) + (p>>2)
  auto kstore = [&]() {
    #pragma unroll
    for (int i = 0; i < 4; i++) {
      int idx = tid + i*128;
      int sp = idx >> 4, c4 = (idx & 15) << 2;
      int j = ((sp & 3) << 3) + (sp >> 2);
      ksh[(c4)*36+j]   = __byte_perm(ka[i].x, kc[i].x, 0x5410);
      ksh[(c4+1)*36+j] = __byte_perm(ka[i].x, kc[i].x, 0x7632);
      ksh[(c4+2)*36+j] = __byte_perm(ka[i].y, kc[i].y, 0x5410);
      ksh[(c4+3)*36+j] = __byte_perm(ka[i].y, kc[i].y, 0x7632);
    }
  };
  auto vasync = [&](__half* vbuf, int s0) {
    #pragma unroll
    for (int i = 0; i < 4; i++) {
      int idx = tid + i*128;
      int s = idx >> 3, c = idx & 7;
      int sr = s0 + s;
      bool ok = sr < TT;
      if (!ok) sr = TT - 1;
      unsigned dst = smem_u32(vbuf + s*72 + c*8);
      asm volatile("cp.async.ca.shared.global [%0], [%1], 16;"
                   :: "r"(dst), "l"(vhg + (size_t)sr*DD + c*8));
      if (c == 0) {
        uint4 one = make_uint4(ok ? 0x00003C00u : 0u, 0u, 0u, 0u);
        *(uint4*)(vbuf + s*72 + 64) = one;
      }
    }
    asm volatile("cp.async.commit_group;" ::: "memory");
  };

  kpref(0);
  vasync((__half*)(sm + SM_VSM), 0);

  const unsigned boffh = ((lid & 7) + ((lid >> 3) & 1)*8)*72 + ((lid >> 4) & 1)*8;
  const unsigned eoffh = ((lid & 7) + ((lid >> 3) & 1)*8)*72 + 64;  // ones tile, .x2
  const __half2 hscale = __float2half2_rn(SCALE_LOG2E);

  float oc[8][4], oce[4];
  #pragma unroll
  for (int nt = 0; nt < 8; nt++)
    #pragma unroll
    for (int r = 0; r < 4; r++) oc[nt][r] = 0.f;
  #pragma unroll
  for (int r = 0; r < 4; r++) oce[r] = 0.f;

  for (int it = 0; it < 16; it++) {
    const int s0 = it * 64;
    const int cur = it & 1;
    __half* vsmc = (__half*)(sm + SM_VSM + cur*9216);

    asm volatile("cp.async.wait_group 0;" ::: "memory");
    __syncthreads();
    kstore();
    __syncthreads();

    // scores straight into mma A fragments
    __half2 fa[4][4];
    #pragma unroll
    for (int k = 0; k < 4; k++)
      #pragma unroll
      for (int r = 0; r < 4; r++) fa[k][r] = __float2half2_rn(0.f);

    #pragma unroll 4
    for (int d = 0; d < 64; d++) {
      unsigned qau = qsh[d*68 + r0], qbu = qsh[d*68 + r1];
      __half2 qa = *(__half2*)&qau, qb = *(__half2*)&qbu;
      __half2 kk[8];
      *(uint4*)kk     = *(const uint4*)(ksh + d*36 + lam*8);
      *(uint4*)(kk+4) = *(const uint4*)(ksh + d*36 + lam*8 + 4);
      #pragma unroll
      for (int k = 0; k < 4; k++) {
        fa[k][0] = __hadd2(fa[k][0], habs2_(__hsub2(qa, kk[2*k])));
        fa[k][1] = __hadd2(fa[k][1], habs2_(__hsub2(qb, kk[2*k])));
        fa[k][2] = __hadd2(fa[k][2], habs2_(__hsub2(qa, kk[2*k+1])));
        fa[k][3] = __hadd2(fa[k][3], habs2_(__hsub2(qb, kk[2*k+1])));
      }
    }

    // p = exp2(scale*sum); mask dead sources on last tile
    #pragma unroll
    for (int k = 0; k < 4; k++)
      #pragma unroll
      for (int r = 0; r < 4; r++) {
        __half2 e = __hmul2(fa[k][r], hscale);
        unsigned ein = *(unsigned*)&e, eout;
        asm("ex2.approx.f16x2 %0, %1;" : "=r"(eout) : "r"(ein));
        if (it == 15) {
          int c = 16*k + 2*lam + ((r >= 2) ? 8 : 0);
          if (s0 + c >= TT) eout = 0u;
        }
        fa[k][r] = *(__half2*)&eout;
      }

    // AV mma + ones column (den)
    const unsigned vsm_s = smem_u32(vsmc);
    #pragma unroll
    for (int np = 0; np < 4; np++) {
      #pragma unroll
      for (int k = 0; k < 4; k++) {
        unsigned b0,b1,b2,b3;
        unsigned bd = vsm_s + (boffh + k*16*72 + np*16)*2;
        asm volatile("ldmatrix.sync.aligned.m8n8.x4.trans.shared.b16 {%0,%1,%2,%3}, [%4];"
          : "=r"(b0),"=r"(b1),"=r"(b2),"=r"(b3) : "r"(bd));
        unsigned a0=*(unsigned*)&fa[k][0], a1=*(unsigned*)&fa[k][1];
        unsigned a2=*(unsigned*)&fa[k][2], a3=*(unsigned*)&fa[k][3];
        asm volatile(
          "mma.sync.aligned.m16n8k16.row.col.f32.f16.f16.f32 "
          "{%0,%1,%2,%3}, {%4,%5,%6,%7}, {%8,%9}, {%0,%1,%2,%3};"
          : "+f"(oc[2*np][0]),"+f"(oc[2*np][1]),"+f"(oc[2*np][2]),"+f"(oc[2*np][3])
          : "r"(a0),"r"(a1),"r"(a2),"r"(a3), "r"(b0),"r"(b1));
        asm volatile(
          "mma.sync.aligned.m16n8k16.row.col.f32.f16.f16.f32 "
          "{%0,%1,%2,%3}, {%4,%5,%6,%7}, {%8,%9}, {%0,%1,%2,%3};"
          : "+f"(oc[2*np+1][0]),"+f"(oc[2*np+1][1]),"+f"(oc[2*np+1][2]),"+f"(oc[2*np+1][3])
          : "r"(a0),"r"(a1),"r"(a2),"r"(a3), "r"(b2),"r"(b3));
      }
    }
    #pragma unroll
    for (int k = 0; k < 4; k++) {   // ones tile: .x2 (cols 64..71 only)
      unsigned b0,b1;
      unsigned bd = vsm_s + (eoffh + k*16*72)*2;
      asm volatile("ldmatrix.sync.aligned.m8n8.x2.trans.shared.b16 {%0,%1}, [%2];"
        : "=r"(b0),"=r"(b1) : "r"(bd));
      unsigned a0=*(unsigned*)&fa[k][0], a1=*(unsigned*)&fa[k][1];
      unsigned a2=*(unsigned*)&fa[k][2], a3=*(unsigned*)&fa[k][3];
      asm volatile(
        "mma.sync.aligned.m16n8k16.row.col.f32.f16.f16.f32 "
        "{%0,%1,%2,%3}, {%4,%5,%6,%7}, {%8,%9}, {%0,%1,%2,%3};"
        : "+f"(oce[0]),"+f"(oce[1]),"+f"(oce[2]),"+f"(oce[3])
        : "r"(a0),"r"(a1),"r"(a2),"r"(a3), "r"(b0),"r"(b1));
    }

    if (it < 15) {
      kpref(s0 + 64);
      vasync((__half*)(sm + SM_VSM + (cur^1)*9216), s0 + 64);
    }
  }

  // epilogue: den held by lanes with lam==0
  float den_lo = __shfl_sync(0xFFFFFFFFu, oce[0], lid & 28);
  float den_hi = __shfl_sync(0xFFFFFFFFu, oce[2], lid & 28);
  const int tlo = t0 + r0, thi = t0 + r1;
  const float invlo = 1.f / (1.f + den_lo);
  const float invhi = 1.f / (1.f + den_hi);
  __half* hop = g_hoh + (size_t)bh*TT*DD;
  #pragma unroll
  for (int nt = 0; nt < 8; nt++) {
    int c = nt*8 + 2*lam;
    if (tlo < TT) {
      __half2 o = __floats2half2_rn(oc[nt][0]*invlo, oc[nt][1]*invlo);
      *(unsigned*)(hop + (size_t)tlo*DD + c) = *(unsigned*)&o;
    }
    if (thi < TT) {
      __half2 o = __floats2half2_rn(oc[nt][2]*invhi, oc[nt][3]*invhi);
      *(unsigned*)(hop + (size_t)thi*DD + c) = *(unsigned*)&o;
    }
  }
}

// K3: head-sum (fp16 in) + ReLU + Wf + residual
__global__ __launch_bounds__(256) void out_kernel(
    const float* __restrict__ x, const float* __restrict__ wf,
    float* __restrict__ out) {
  __shared__ float r[4][64];
  __shared__ float wfs[64*65];
  const int tl = threadIdx.x >> 6, w = threadIdx.x & 63;
  const int token = blockIdx.x*4 + tl, b = token / TT, t = token - b*TT;
  for (int i = threadIdx.x; i < 4160; i += 256) wfs[i] = wf[i];
  float s = 0.f;
  #pragma unroll
  for (int h = 0; h < NHH; h++)
    s += __half2float(g_hoh[((size_t)(b*NHH + h)*TT + t)*DD + w]);
  r[tl][w] = fmaxf(s, 0.f);
  __syncthreads();
  float acc = wfs[w*65 + 64];
  #pragma unroll 8
  for (int k = 0; k < 64; k++) acc += wfs[w*65 + k] * r[tl][k];
  out[(size_t)token*DD + w] = x[(size_t)token*DD + w] + acc;
}

extern "C" void kernel_launch(void* const* d_in, const int* in_sizes, int n_in,
                              void* d_out, int out_size) {
  const float* x  = (const float*)d_in[0];
  const float* wq = (const float*)d_in[1];
  const float* wv = (const float*)d_in[2];
  const float* wk = (const float*)d_in[3];
  const float* wf = (const float*)d_in[4];
  float* out = (float*)d_out;
  (void)in_sizes; (void)n_in; (void)out_size;

  cudaFuncSetAttribute(attn_kernel, cudaFuncAttributeMaxDynamicSharedMemorySize,
                       ATTN_SMEM);
  kpack_kernel<<<BB*TT/32, 256>>>(x, wk);
  qv_kernel<<<dim3(8000/64, 512/64, 2), 256>>>(x, wq, wv);
  attn_kernel<<<dim3(16, NHH, BB), 128, ATTN_SMEM>>>();
  out_kernel<<<8000/4, 256>>>(x, wf, out);
}

// round 13
// speedup vs baseline: 1.0549x; 1.0549x over previous
#include <cuda_runtime.h>
#include <cuda_fp16.h>
#include <cstdint>

#define BB  8
#define TT  1000
#define NHH 8
#define DD  64
#define SCALE_LOG2E (-0.18033688011112042f)
#define POS2SCALE   (0.36067376022224084f)

__device__ __half g_qh[BB*NHH*TT*DD];
__device__ __half g_kh[BB*NHH*TT*DD];
__device__ __half g_vh[BB*NHH*TT*DD];
__device__ __half g_k1h[BB*NHH*TT];       // K1[s] * SCALE_LOG2E
__device__ __half g_hoh[BB*NHH*TT*DD];

__device__ __forceinline__ unsigned smem_u32(const void* p) {
  return (unsigned)__cvta_generic_to_shared(p);
}

// K0: k = x*wk -> fp16 (+ prescaled row sum K1)
__global__ __launch_bounds__(256) void kpack_kernel(
    const float* __restrict__ x, const float* __restrict__ wk) {
  __shared__ float xs[32][68];
  __shared__ float wks[512];
  const int tid = threadIdx.x, tok0 = blockIdx.x * 32;
  for (int i = tid; i < 512; i += 256) wks[i] = wk[i];
  for (int i = tid; i < 512; i += 256) {
    int tl = i >> 4, k4 = (i & 15) << 2;
    float4 v = *(const float4*)&x[(tok0 + tl)*DD + k4];
    xs[tl][k4] = v.x; xs[tl][k4+1] = v.y; xs[tl][k4+2] = v.z; xs[tl][k4+3] = v.w;
  }
  __syncthreads();
  const int h = tid >> 5, tl = tid & 31;
  const int gt = tok0 + tl, b = gt / TT, t = gt - b*TT;
  __half* dst = g_kh + ((size_t)(b*NHH + h)*TT + t)*DD;
  float sum = 0.f;
  #pragma unroll
  for (int c = 0; c < 8; c++) {
    int d = c*8;
    float p[8];
    #pragma unroll
    for (int j = 0; j < 8; j++) { p[j] = xs[tl][d+j]*wks[h*64+d+j]; sum += p[j]; }
    __half2 h0 = __floats2half2_rn(p[0], p[1]);
    __half2 h1 = __floats2half2_rn(p[2], p[3]);
    __half2 h2 = __floats2half2_rn(p[4], p[5]);
    __half2 h3 = __floats2half2_rn(p[6], p[7]);
    uint4 o; o.x=*(unsigned*)&h0; o.y=*(unsigned*)&h1; o.z=*(unsigned*)&h2; o.w=*(unsigned*)&h3;
    *(uint4*)(dst + d) = o;
  }
  g_k1h[(size_t)(b*NHH + h)*TT + t] = __float2half_rn(sum * SCALE_LOG2E);
}

// K1: Q/V projection -> fp16 [b,h][t][d]
__global__ __launch_bounds__(256) void qv_kernel(
    const float* __restrict__ x, const float* __restrict__ wq,
    const float* __restrict__ wv) {
  const float* w = blockIdx.z ? wv : wq;
  __half* dstg   = blockIdx.z ? g_vh : g_qh;
  const int m0 = blockIdx.x * 64, n0 = blockIdx.y * 64;
  __shared__ float xs[64*68];
  __shared__ float ws[64*68];
  const int tid = threadIdx.x;
  for (int i = tid; i < 1024; i += 256) {
    int m = i >> 4, k4 = (i & 15) << 2;
    float4 v4 = *(const float4*)&x[(m0 + m)*DD + k4];
    xs[(k4)*68+m]=v4.x; xs[(k4+1)*68+m]=v4.y; xs[(k4+2)*68+m]=v4.z; xs[(k4+3)*68+m]=v4.w;
  }
  for (int i = tid; i < 4096; i += 256) {
    int n = i >> 6, k = i & 63;
    ws[k*68 + n] = w[(n0 + n)*65 + k];
  }
  __syncthreads();
  const int tm = (tid >> 4) * 4, tn = (tid & 15) * 4;
  float acc[4][4];
  #pragma unroll
  for (int i = 0; i < 4; i++)
    #pragma unroll
    for (int j = 0; j < 4; j++) acc[i][j] = 0.f;
  #pragma unroll 8
  for (int k = 0; k < 64; k++) {
    float4 a4 = *(const float4*)&xs[k*68 + tm];
    float4 b4 = *(const float4*)&ws[k*68 + tn];
    float av[4] = {a4.x,a4.y,a4.z,a4.w}, bv[4] = {b4.x,b4.y,b4.z,b4.w};
    #pragma unroll
    for (int i = 0; i < 4; i++)
      #pragma unroll
      for (int j = 0; j < 4; j++) acc[i][j] += av[i]*bv[j];
  }
  const int n = n0 + tn, h = n >> 6, d0 = n & 63;
  float b0=w[n*65+64], b1=w[(n+1)*65+64], b2=w[(n+2)*65+64], b3=w[(n+3)*65+64];
  #pragma unroll
  for (int i = 0; i < 4; i++) {
    int m = m0 + tm + i, b = m / TT, t = m - b*TT;
    __half2 h01 = __floats2half2_rn(acc[i][0]+b0, acc[i][1]+b1);
    __half2 h23 = __floats2half2_rn(acc[i][2]+b2, acc[i][3]+b3);
    uint2 o; o.x=*(unsigned*)&h01; o.y=*(unsigned*)&h23;
    *(uint2*)(dstg + ((size_t)(b*NHH+h)*TT + t)*DD + d0) = o;
  }
}

// K2 smem: qsh dup [64][68]u @0; ksh pair-shuffled [64][36]u @17408;
// vsm half[64][72] x2 @26624; q1sh 64h @45056; k1sh 36u @45184. tot 45328
#define SM_QSH   0
#define SM_KSH   17408
#define SM_VSM   26624
#define SM_Q1    45056
#define SM_K1    45184
#define ATTN_SMEM 45328

__global__ __launch_bounds__(128, 5) void attn_kernel() {
  extern __shared__ char sm[];
  unsigned* qsh  = (unsigned*)(sm + SM_QSH);
  unsigned* ksh  = (unsigned*)(sm + SM_KSH);
  __half*   q1sh = (__half*)(sm + SM_Q1);
  unsigned* k1sh = (unsigned*)(sm + SM_K1);

  const int tid = threadIdx.x, wid = tid >> 5, lid = tid & 31;
  const int bh = blockIdx.z*NHH + blockIdx.y;
  const int t0 = blockIdx.x * 64;
  const int lam = lid & 3;
  const int r0 = wid*16 + (lid >> 2), r1 = r0 + 8;

  const __half* qhg = g_qh + (size_t)bh*TT*DD;
  const __half* khg = g_kh + (size_t)bh*TT*DD;
  const __half* vhg = g_vh + (size_t)bh*TT*DD;
  const __half* k1g = g_k1h + (size_t)bh*TT;

  // q -> qsh[d][t] duplicated
  for (int i = tid; i < 1024; i += 128) {
    int t = i >> 4, c4 = (i & 15) << 2;
    int tr = t0 + t; if (tr >= TT) tr = TT - 1;
    uint2 a = *(const uint2*)(qhg + (size_t)tr*DD + c4);
    qsh[(c4)*68+t]   = __byte_perm(a.x, a.x, 0x1010);
    qsh[(c4+1)*68+t] = __byte_perm(a.x, a.x, 0x3232);
    qsh[(c4+2)*68+t] = __byte_perm(a.y, a.y, 0x1010);
    qsh[(c4+3)*68+t] = __byte_perm(a.y, a.y, 0x3232);
  }
  // Q1 row sums (prescaled)
  if (tid < 64) {
    int tr = t0 + tid; if (tr >= TT) tr = TT - 1;
    const uint4* qr = (const uint4*)(qhg + (size_t)tr*DD);
    float s = 0.f;
    #pragma unroll
    for (int i = 0; i < 8; i++) {
      uint4 v = qr[i];
      __half2* hp = (__half2*)&v;
      #pragma unroll
      for (int j = 0; j < 4; j++) { float2 f = __half22float2(hp[j]); s += f.x + f.y; }
    }
    q1sh[tid] = __float2half_rn(s * SCALE_LOG2E);
  }

  uint2 ka[4], kc[4];
  unsigned k1u[4];
  auto kpref = [&](int s0) {
    #pragma unroll
    for (int i = 0; i < 4; i++) {
      int idx = tid + i*128;
      int sp = idx >> 4, c4 = (idx & 15) << 2;
      int sA = s0 + 2*sp, sB = sA + 1;
      if ((tid & 15) == 0) {
        int sE = sA; if (sE > TT - 2) sE = TT - 2;
        k1u[i] = *(const unsigned*)(k1g + sE);
      }
      if (sA >= TT) sA = TT - 1;
      if (sB >= TT) sB = TT - 1;
      ka[i] = *(const uint2*)(khg + (size_t)sA*DD + c4);
      kc[i] = *(const uint2*)(khg + (size_t)sB*DD + c4);
    }
  };
  auto kstore = [&]() {
    #pragma unroll
    for (int i = 0; i < 4; i++) {
      int idx = tid + i*128;
      int sp = idx >> 4, c4 = (idx & 15) << 2;
      int j = ((sp & 3) << 3) + (sp >> 2);
      ksh[(c4)*36+j]   = __byte_perm(ka[i].x, kc[i].x, 0x5410);
      ksh[(c4+1)*36+j] = __byte_perm(ka[i].x, kc[i].x, 0x7632);
      ksh[(c4+2)*36+j] = __byte_perm(ka[i].y, kc[i].y, 0x5410);
      ksh[(c4+3)*36+j] = __byte_perm(ka[i].y, kc[i].y, 0x7632);
      if ((tid & 15) == 0) k1sh[j] = k1u[i];
    }
  };
  auto vasync = [&](__half* vbuf, int s0) {
    #pragma unroll
    for (int i = 0; i < 4; i++) {
      int idx = tid + i*128;
      int s = idx >> 3, c = idx & 7;
      int sr = s0 + s;
      bool ok = sr < TT;
      if (!ok) sr = TT - 1;
      unsigned dst = smem_u32(vbuf + s*72 + c*8);
      asm volatile("cp.async.ca.shared.global [%0], [%1], 16;"
                   :: "r"(dst), "l"(vhg + (size_t)sr*DD + c*8));
      if (c == 0) {
        uint4 one = make_uint4(ok ? 0x00003C00u : 0u, 0u, 0u, 0u);
        *(uint4*)(vbuf + s*72 + 64) = one;
      }
    }
    asm volatile("cp.async.commit_group;" ::: "memory");
  };

  kpref(0);
  vasync((__half*)(sm + SM_VSM), 0);
  __syncthreads();   // q1sh visible
  const __half2 q1a2 = __half2half2(q1sh[r0]);
  const __half2 q1b2 = __half2half2(q1sh[r1]);

  const unsigned boffh = ((lid & 7) + ((lid >> 3) & 1)*8)*72 + ((lid >> 4) & 1)*8;
  const unsigned eoffh = ((lid & 7) + ((lid >> 3) & 1)*8)*72 + 64;
  const __half2 pos2 = __float2half2_rn(POS2SCALE);

  float oc[8][4], oce[4];
  #pragma unroll
  for (int nt = 0; nt < 8; nt++)
    #pragma unroll
    for (int r = 0; r < 4; r++) oc[nt][r] = 0.f;
  #pragma unroll
  for (int r = 0; r < 4; r++) oce[r] = 0.f;

  for (int it = 0; it < 16; it++) {
    const int s0 = it * 64;
    const int cur = it & 1;
    __half* vsmc = (__half*)(sm + SM_VSM + cur*9216);

    asm volatile("cp.async.wait_group 0;" ::: "memory");
    __syncthreads();
    kstore();
    __syncthreads();

    // M = sum_d min(q,k), straight into mma A fragment slots
    __half2 fa[4][4];
    #pragma unroll
    for (int k = 0; k < 4; k++)
      #pragma unroll
      for (int r = 0; r < 4; r++) fa[k][r] = __float2half2_rn(0.f);

    #pragma unroll 4
    for (int d = 0; d < 64; d++) {
      unsigned qau = qsh[d*68 + r0], qbu = qsh[d*68 + r1];
      __half2 qa = *(__half2*)&qau, qb = *(__half2*)&qbu;
      __half2 kk[8];
      *(uint4*)kk     = *(const uint4*)(ksh + d*36 + lam*8);
      *(uint4*)(kk+4) = *(const uint4*)(ksh + d*36 + lam*8 + 4);
      #pragma unroll
      for (int k = 0; k < 4; k++) {
        fa[k][0] = __hadd2(fa[k][0], __hmin2(qa, kk[2*k]));
        fa[k][1] = __hadd2(fa[k][1], __hmin2(qb, kk[2*k]));
        fa[k][2] = __hadd2(fa[k][2], __hmin2(qa, kk[2*k+1]));
        fa[k][3] = __hadd2(fa[k][3], __hmin2(qb, kk[2*k+1]));
      }
    }

    // p = exp2(c_qs + pos2*M); mask dead sources on last tile
    #pragma unroll
    for (int k = 0; k < 4; k++) {
      unsigned k1a = k1sh[lam*8 + 2*k], k1b = k1sh[lam*8 + 2*k + 1];
      __half2 k1ah = *(__half2*)&k1a, k1bh = *(__half2*)&k1b;
      __half2 cc[4];
      cc[0] = __hadd2(q1a2, k1ah);
      cc[1] = __hadd2(q1b2, k1ah);
      cc[2] = __hadd2(q1a2, k1bh);
      cc[3] = __hadd2(q1b2, k1bh);
      #pragma unroll
      for (int r = 0; r < 4; r++) {
        __half2 e = __hfma2(fa[k][r], pos2, cc[r]);
        unsigned ein = *(unsigned*)&e, eout;
        asm("ex2.approx.f16x2 %0, %1;" : "=r"(eout) : "r"(ein));
        if (it == 15) {
          int c = 16*k + 2*lam + ((r >= 2) ? 8 : 0);
          if (s0 + c >= TT) eout = 0u;
        }
        fa[k][r] = *(__half2*)&eout;
      }
    }

    // AV mma + ones column (den)
    const unsigned vsm_s = smem_u32(vsmc);
    #pragma unroll
    for (int np = 0; np < 4; np++) {
      #pragma unroll
      for (int k = 0; k < 4; k++) {
        unsigned b0,b1,b2,b3;
        unsigned bd = vsm_s + (boffh + k*16*72 + np*16)*2;
        asm volatile("ldmatrix.sync.aligned.m8n8.x4.trans.shared.b16 {%0,%1,%2,%3}, [%4];"
          : "=r"(b0),"=r"(b1),"=r"(b2),"=r"(b3) : "r"(bd));
        unsigned a0=*(unsigned*)&fa[k][0], a1=*(unsigned*)&fa[k][1];
        unsigned a2=*(unsigned*)&fa[k][2], a3=*(unsigned*)&fa[k][3];
        asm volatile(
          "mma.sync.aligned.m16n8k16.row.col.f32.f16.f16.f32 "
          "{%0,%1,%2,%3}, {%4,%5,%6,%7}, {%8,%9}, {%0,%1,%2,%3};"
          : "+f"(oc[2*np][0]),"+f"(oc[2*np][1]),"+f"(oc[2*np][2]),"+f"(oc[2*np][3])
          : "r"(a0),"r"(a1),"r"(a2),"r"(a3), "r"(b0),"r"(b1));
        asm volatile(
          "mma.sync.aligned.m16n8k16.row.col.f32.f16.f16.f32 "
          "{%0,%1,%2,%3}, {%4,%5,%6,%7}, {%8,%9}, {%0,%1,%2,%3};"
          : "+f"(oc[2*np+1][0]),"+f"(oc[2*np+1][1]),"+f"(oc[2*np+1][2]),"+f"(oc[2*np+1][3])
          : "r"(a0),"r"(a1),"r"(a2),"r"(a3), "r"(b2),"r"(b3));
      }
    }
    #pragma unroll
    for (int k = 0; k < 4; k++) {
      unsigned b0,b1;
      unsigned bd = vsm_s + (eoffh + k*16*72)*2;
      asm volatile("ldmatrix.sync.aligned.m8n8.x2.trans.shared.b16 {%0,%1}, [%2];"
        : "=r"(b0),"=r"(b1) : "r"(bd));
      unsigned a0=*(unsigned*)&fa[k][0], a1=*(unsigned*)&fa[k][1];
      unsigned a2=*(unsigned*)&fa[k][2], a3=*(unsigned*)&fa[k][3];
      asm volatile(
        "mma.sync.aligned.m16n8k16.row.col.f32.f16.f16.f32 "
        "{%0,%1,%2,%3}, {%4,%5,%6,%7}, {%8,%9}, {%0,%1,%2,%3};"
        : "+f"(oce[0]),"+f"(oce[1]),"+f"(oce[2]),"+f"(oce[3])
        : "r"(a0),"r"(a1),"r"(a2),"r"(a3), "r"(b0),"r"(b1));
    }

    if (it < 15) {
      kpref(s0 + 64);
      vasync((__half*)(sm + SM_VSM + (cur^1)*9216), s0 + 64);
    }
  }

  // epilogue
  float den_lo = __shfl_sync(0xFFFFFFFFu, oce[0], lid & 28);
  float den_hi = __shfl_sync(0xFFFFFFFFu, oce[2], lid & 28);
  const int tlo = t0 + r0, thi = t0 + r1;
  const float invlo = 1.f / (1.f + den_lo);
  const float invhi = 1.f / (1.f + den_hi);
  __half* hop = g_hoh + (size_t)bh*TT*DD;
  #pragma unroll
  for (int nt = 0; nt < 8; nt++) {
    int c = nt*8 + 2*lam;
    if (tlo < TT) {
      __half2 o = __floats2half2_rn(oc[nt][0]*invlo, oc[nt][1]*invlo);
      *(unsigned*)(hop + (size_t)tlo*DD + c) = *(unsigned*)&o;
    }
    if (thi < TT) {
      __half2 o = __floats2half2_rn(oc[nt][2]*invhi, oc[nt][3]*invhi);
      *(unsigned*)(hop + (size_t)thi*DD + c) = *(unsigned*)&o;
    }
  }
}

// K3: head-sum (fp16 in) + ReLU + Wf + residual
__global__ __launch_bounds__(256) void out_kernel(
    const float* __restrict__ x, const float* __restrict__ wf,
    float* __restrict__ out) {
  __shared__ float r[4][64];
  __shared__ float wfs[64*65];
  const int tl = threadIdx.x >> 6, w = threadIdx.x & 63;
  const int token = blockIdx.x*4 + tl, b = token / TT, t = token - b*TT;
  for (int i = threadIdx.x; i < 4160; i += 256) wfs[i] = wf[i];
  float s = 0.f;
  #pragma unroll
  for (int h = 0; h < NHH; h++)
    s += __half2float(g_hoh[((size_t)(b*NHH + h)*TT + t)*DD + w]);
  r[tl][w] = fmaxf(s, 0.f);
  __syncthreads();
  float acc = wfs[w*65 + 64];
  #pragma unroll 8
  for (int k = 0; k < 64; k++) acc += wfs[w*65 + k] * r[tl][k];
  out[(size_t)token*DD + w] = x[(size_t)token*DD + w] + acc;
}

extern "C" void kernel_launch(void* const* d_in, const int* in_sizes, int n_in,
                              void* d_out, int out_size) {
  const float* x  = (const float*)d_in[0];
  const float* wq = (const float*)d_in[1];
  const float* wv = (const float*)d_in[2];
  const float* wk = (const float*)d_in[3];
  const float* wf = (const float*)d_in[4];
  float* out = (float*)d_out;
  (void)in_sizes; (void)n_in; (void)out_size;

  cudaFuncSetAttribute(attn_kernel, cudaFuncAttributeMaxDynamicSharedMemorySize,
                       ATTN_SMEM);
  kpack_kernel<<<BB*TT/32, 256>>>(x, wk);
  qv_kernel<<<dim3(8000/64, 512/64, 2), 256>>>(x, wq, wv);
  attn_kernel<<<dim3(16, NHH, BB), 128, ATTN_SMEM>>>();
  out_kernel<<<8000/4, 256>>>(x, wf, out);
}

// round 14
// speedup vs baseline: 1.1220x; 1.0636x over previous
#include <cuda_runtime.h>
#include <cuda_fp16.h>
#include <cstdint>

#define BB  8
#define TT  1000
#define NHH 8
#define DD  64
#define SCALE_LOG2E (-0.18033688011112042f)
#define POS2SCALE   (0.36067376022224084f)

__device__ __half g_qh[BB*NHH*TT*DD];
__device__ __half g_kh[BB*NHH*TT*DD];
__device__ __half g_vh[BB*NHH*TT*DD];
__device__ __half g_k1h[BB*NHH*TT];       // K1[s] * SCALE_LOG2E
__device__ __half g_hoh[BB*NHH*TT*DD];

__device__ __forceinline__ unsigned smem_u32(const void* p) {
  return (unsigned)__cvta_generic_to_shared(p);
}
__device__ __forceinline__ unsigned duph_(float v) {
  __half h = __float2half_rn(v);
  unsigned u = (unsigned)*(unsigned short*)&h;
  return u | (u << 16);
}

// K0: fused projections. z=0: q (fp16x2 GEMM) -> g_qh; z=1: v -> g_vh;
// z=2 (y==0 only): k = x*wk -> g_kh + prescaled row sums g_k1h.
__global__ __launch_bounds__(256) void proj_kernel(
    const float* __restrict__ x, const float* __restrict__ wq,
    const float* __restrict__ wv, const float* __restrict__ wk) {
  __shared__ unsigned xs2[64*68];   // z<2: dup half2 [k][m]; z=2: float xs[64][68]
  __shared__ unsigned ws2[64*36];   // half2 n-pairs [k][np]
  __shared__ float    wks[512];
  const int tid = threadIdx.x;
  const int z = blockIdx.z;

  if (z == 2) {
    if (blockIdx.y) return;
    float* xs = (float*)xs2;                       // [64][68]
    const int tok0 = blockIdx.x * 64;
    for (int i = tid; i < 512; i += 256) wks[i] = wk[i];
    for (int i = tid; i < 1024; i += 256) {
      int tl = i >> 4, k4 = (i & 15) << 2;
      float4 v = *(const float4*)&x[(tok0 + tl)*DD + k4];
      xs[tl*68+k4] = v.x; xs[tl*68+k4+1] = v.y;
      xs[tl*68+k4+2] = v.z; xs[tl*68+k4+3] = v.w;
    }
    __syncthreads();
    const int h = tid >> 5, tl0 = tid & 31;
    #pragma unroll
    for (int hf = 0; hf < 2; hf++) {
      int tl = tl0 + hf*32;
      int gt = tok0 + tl, b = gt / TT, t = gt - b*TT;
      __half* dst = g_kh + ((size_t)(b*NHH + h)*TT + t)*DD;
      float sum = 0.f;
      #pragma unroll
      for (int c = 0; c < 8; c++) {
        int d = c*8;
        float p[8];
        #pragma unroll
        for (int j = 0; j < 8; j++) { p[j] = xs[tl*68+d+j]*wks[h*64+d+j]; sum += p[j]; }
        __half2 h0 = __floats2half2_rn(p[0], p[1]);
        __half2 h1 = __floats2half2_rn(p[2], p[3]);
        __half2 h2 = __floats2half2_rn(p[4], p[5]);
        __half2 h3 = __floats2half2_rn(p[6], p[7]);
        uint4 o; o.x=*(unsigned*)&h0; o.y=*(unsigned*)&h1; o.z=*(unsigned*)&h2; o.w=*(unsigned*)&h3;
        *(uint4*)(dst + d) = o;
      }
      g_k1h[(size_t)(b*NHH + h)*TT + t] = __float2half_rn(sum * SCALE_LOG2E);
    }
    return;
  }

  // ---- q/v projection in fp16x2 ----
  const float* w = z ? wv : wq;
  __half* dstg   = z ? g_vh : g_qh;
  const int m0 = blockIdx.x * 64, n0 = blockIdx.y * 64;

  for (int i = tid; i < 1024; i += 256) {       // x -> dup half2 [k][m]
    int m = i >> 4, k4 = (i & 15) << 2;
    float4 v4 = *(const float4*)&x[(m0 + m)*DD + k4];
    xs2[(k4)*68+m]   = duph_(v4.x);
    xs2[(k4+1)*68+m] = duph_(v4.y);
    xs2[(k4+2)*68+m] = duph_(v4.z);
    xs2[(k4+3)*68+m] = duph_(v4.w);
  }
  for (int i = tid; i < 2048; i += 256) {       // w -> n-pair half2 [k][np]
    int np = i >> 6, k = i & 63;
    float a = w[(n0 + 2*np)*65 + k];
    float b = w[(n0 + 2*np + 1)*65 + k];
    __half2 h = __floats2half2_rn(a, b);
    ws2[k*36 + np] = *(unsigned*)&h;
  }
  __syncthreads();

  const int tm = (tid >> 4) * 4, tn = (tid & 15) * 4, tnp = tn >> 1;
  __half2 acc2[4][2];
  #pragma unroll
  for (int i = 0; i < 4; i++) {
    acc2[i][0] = __float2half2_rn(0.f);
    acc2[i][1] = __float2half2_rn(0.f);
  }
  #pragma unroll 8
  for (int k = 0; k < 64; k++) {
    uint4 xq = *(const uint4*)&xs2[k*68 + tm];
    uint2 wp = *(const uint2*)&ws2[k*36 + tnp];
    __half2 xv[4]; *(uint4*)xv = xq;
    __half2 w0 = *(__half2*)&wp.x, w1 = *(__half2*)&wp.y;
    #pragma unroll
    for (int i = 0; i < 4; i++) {
      acc2[i][0] = __hfma2(xv[i], w0, acc2[i][0]);
      acc2[i][1] = __hfma2(xv[i], w1, acc2[i][1]);
    }
  }

  const int n = n0 + tn, h = n >> 6, d0 = n & 63;
  __half2 b01 = __floats2half2_rn(w[n*65+64],     w[(n+1)*65+64]);
  __half2 b23 = __floats2half2_rn(w[(n+2)*65+64], w[(n+3)*65+64]);
  #pragma unroll
  for (int i = 0; i < 4; i++) {
    int m = m0 + tm + i, b = m / TT, t = m - b*TT;
    __half2 o0 = __hadd2(acc2[i][0], b01);
    __half2 o1 = __hadd2(acc2[i][1], b23);
    uint2 o; o.x = *(unsigned*)&o0; o.y = *(unsigned*)&o1;
    *(uint2*)(dstg + ((size_t)(b*NHH+h)*TT + t)*DD + d0) = o;
  }
}

// K2 smem: qsh dup [64][68]u @0; ksh pair-shuffled [64][36]u @17408;
// vsm half[64][72] x2 @26624; q1sh 64h @45056; k1sh 36u @45184. tot 45328
#define SM_QSH   0
#define SM_KSH   17408
#define SM_VSM   26624
#define SM_Q1    45056
#define SM_K1    45184
#define ATTN_SMEM 45328

__global__ __launch_bounds__(128, 5) void attn_kernel() {
  extern __shared__ char sm[];
  unsigned* qsh  = (unsigned*)(sm + SM_QSH);
  unsigned* ksh  = (unsigned*)(sm + SM_KSH);
  __half*   q1sh = (__half*)(sm + SM_Q1);
  unsigned* k1sh = (unsigned*)(sm + SM_K1);

  const int tid = threadIdx.x, wid = tid >> 5, lid = tid & 31;
  const int bh = blockIdx.z*NHH + blockIdx.y;
  const int t0 = blockIdx.x * 64;
  const int lam = lid & 3;
  const int r0 = wid*16 + (lid >> 2), r1 = r0 + 8;

  const __half* qhg = g_qh + (size_t)bh*TT*DD;
  const __half* khg = g_kh + (size_t)bh*TT*DD;
  const __half* vhg = g_vh + (size_t)bh*TT*DD;
  const __half* k1g = g_k1h + (size_t)bh*TT;

  for (int i = tid; i < 1024; i += 128) {
    int t = i >> 4, c4 = (i & 15) << 2;
    int tr = t0 + t; if (tr >= TT) tr = TT - 1;
    uint2 a = *(const uint2*)(qhg + (size_t)tr*DD + c4);
    qsh[(c4)*68+t]   = __byte_perm(a.x, a.x, 0x1010);
    qsh[(c4+1)*68+t] = __byte_perm(a.x, a.x, 0x3232);
    qsh[(c4+2)*68+t] = __byte_perm(a.y, a.y, 0x1010);
    qsh[(c4+3)*68+t] = __byte_perm(a.y, a.y, 0x3232);
  }
  if (tid < 64) {
    int tr = t0 + tid; if (tr >= TT) tr = TT - 1;
    const uint4* qr = (const uint4*)(qhg + (size_t)tr*DD);
    float s = 0.f;
    #pragma unroll
    for (int i = 0; i < 8; i++) {
      uint4 v = qr[i];
      __half2* hp = (__half2*)&v;
      #pragma unroll
      for (int j = 0; j < 4; j++) { float2 f = __half22float2(hp[j]); s += f.x + f.y; }
    }
    q1sh[tid] = __float2half_rn(s * SCALE_LOG2E);
  }

  uint2 ka[4], kc[4];
  unsigned k1u[4];
  auto kpref = [&](int s0) {
    #pragma unroll
    for (int i = 0; i < 4; i++) {
      int idx = tid + i*128;
      int sp = idx >> 4, c4 = (idx & 15) << 2;
      int sA = s0 + 2*sp, sB = sA + 1;
      if ((tid & 15) == 0) {
        int sE = sA; if (sE > TT - 2) sE = TT - 2;
        k1u[i] = *(const unsigned*)(k1g + sE);
      }
      if (sA >= TT) sA = TT - 1;
      if (sB >= TT) sB = TT - 1;
      ka[i] = *(const uint2*)(khg + (size_t)sA*DD + c4);
      kc[i] = *(const uint2*)(khg + (size_t)sB*DD + c4);
    }
  };
  auto kstore = [&]() {
    #pragma unroll
    for (int i = 0; i < 4; i++) {
      int idx = tid + i*128;
      int sp = idx >> 4, c4 = (idx & 15) << 2;
      int j = ((sp & 3) << 3) + (sp >> 2);
      ksh[(c4)*36+j]   = __byte_perm(ka[i].x, kc[i].x, 0x5410);
      ksh[(c4+1)*36+j] = __byte_perm(ka[i].x, kc[i].x, 0x7632);
      ksh[(c4+2)*36+j] = __byte_perm(ka[i].y, kc[i].y, 0x5410);
      ksh[(c4+3)*36+j] = __byte_perm(ka[i].y, kc[i].y, 0x7632);
      if ((tid & 15) == 0) k1sh[j] = k1u[i];
    }
  };
  auto vasync = [&](__half* vbuf, int s0) {
    #pragma unroll
    for (int i = 0; i < 4; i++) {
      int idx = tid + i*128;
      int s = idx >> 3, c = idx & 7;
      int sr = s0 + s;
      bool ok = sr < TT;
      if (!ok) sr = TT - 1;
      unsigned dst = smem_u32(vbuf + s*72 + c*8);
      asm volatile("cp.async.ca.shared.global [%0], [%1], 16;"
                   :: "r"(dst), "l"(vhg + (size_t)sr*DD + c*8));
      if (c == 0) {
        uint4 one = make_uint4(ok ? 0x00003C00u : 0u, 0u, 0u, 0u);
        *(uint4*)(vbuf + s*72 + 64) = one;
      }
    }
    asm volatile("cp.async.commit_group;" ::: "memory");
  };

  kpref(0);
  vasync((__half*)(sm + SM_VSM), 0);
  __syncthreads();
  const __half2 q1a2 = __half2half2(q1sh[r0]);
  const __half2 q1b2 = __half2half2(q1sh[r1]);

  const unsigned boffh = ((lid & 7) + ((lid >> 3) & 1)*8)*72 + ((lid >> 4) & 1)*8;
  const unsigned eoffh = ((lid & 7) + ((lid >> 3) & 1)*8)*72 + 64;
  const __half2 pos2 = __float2half2_rn(POS2SCALE);

  float oc[8][4], oce[4];
  #pragma unroll
  for (int nt = 0; nt < 8; nt++)
    #pragma unroll
    for (int r = 0; r < 4; r++) oc[nt][r] = 0.f;
  #pragma unroll
  for (int r = 0; r < 4; r++) oce[r] = 0.f;

  for (int it = 0; it < 16; it++) {
    const int s0 = it * 64;
    const int cur = it & 1;
    __half* vsmc = (__half*)(sm + SM_VSM + cur*9216);

    asm volatile("cp.async.wait_group 0;" ::: "memory");
    __syncthreads();
    kstore();
    __syncthreads();

    __half2 fa[4][4];
    #pragma unroll
    for (int k = 0; k < 4; k++)
      #pragma unroll
      for (int r = 0; r < 4; r++) fa[k][r] = __float2half2_rn(0.f);

    #pragma unroll 4
    for (int d = 0; d < 64; d++) {
      unsigned qau = qsh[d*68 + r0], qbu = qsh[d*68 + r1];
      __half2 qa = *(__half2*)&qau, qb = *(__half2*)&qbu;
      __half2 kk[8];
      *(uint4*)kk     = *(const uint4*)(ksh + d*36 + lam*8);
      *(uint4*)(kk+4) = *(const uint4*)(ksh + d*36 + lam*8 + 4);
      #pragma unroll
      for (int k = 0; k < 4; k++) {
        fa[k][0] = __hadd2(fa[k][0], __hmin2(qa, kk[2*k]));
        fa[k][1] = __hadd2(fa[k][1], __hmin2(qb, kk[2*k]));
        fa[k][2] = __hadd2(fa[k][2], __hmin2(qa, kk[2*k+1]));
        fa[k][3] = __hadd2(fa[k][3], __hmin2(qb, kk[2*k+1]));
      }
    }

    #pragma unroll
    for (int k = 0; k < 4; k++) {
      unsigned k1a = k1sh[lam*8 + 2*k], k1b = k1sh[lam*8 + 2*k + 1];
      __half2 k1ah = *(__half2*)&k1a, k1bh = *(__half2*)&k1b;
      __half2 cc[4];
      cc[0] = __hadd2(q1a2, k1ah);
      cc[1] = __hadd2(q1b2, k1ah);
      cc[2] = __hadd2(q1a2, k1bh);
      cc[3] = __hadd2(q1b2, k1bh);
      #pragma unroll
      for (int r = 0; r < 4; r++) {
        __half2 e = __hfma2(fa[k][r], pos2, cc[r]);
        unsigned ein = *(unsigned*)&e, eout;
        asm("ex2.approx.f16x2 %0, %1;" : "=r"(eout) : "r"(ein));
        if (it == 15) {
          int c = 16*k + 2*lam + ((r >= 2) ? 8 : 0);
          if (s0 + c >= TT) eout = 0u;
        }
        fa[k][r] = *(__half2*)&eout;
      }
    }

    const unsigned vsm_s = smem_u32(vsmc);
    #pragma unroll
    for (int np = 0; np < 4; np++) {
      #pragma unroll
      for (int k = 0; k < 4; k++) {
        unsigned b0,b1,b2,b3;
        unsigned bd = vsm_s + (boffh + k*16*72 + np*16)*2;
        asm volatile("ldmatrix.sync.aligned.m8n8.x4.trans.shared.b16 {%0,%1,%2,%3}, [%4];"
          : "=r"(b0),"=r"(b1),"=r"(b2),"=r"(b3) : "r"(bd));
        unsigned a0=*(unsigned*)&fa[k][0], a1=*(unsigned*)&fa[k][1];
        unsigned a2=*(unsigned*)&fa[k][2], a3=*(unsigned*)&fa[k][3];
        asm volatile(
          "mma.sync.aligned.m16n8k16.row.col.f32.f16.f16.f32 "
          "{%0,%1,%2,%3}, {%4,%5,%6,%7}, {%8,%9}, {%0,%1,%2,%3};"
          : "+f"(oc[2*np][0]),"+f"(oc[2*np][1]),"+f"(oc[2*np][2]),"+f"(oc[2*np][3])
          : "r"(a0),"r"(a1),"r"(a2),"r"(a3), "r"(b0),"r"(b1));
        asm volatile(
          "mma.sync.aligned.m16n8k16.row.col.f32.f16.f16.f32 "
          "{%0,%1,%2,%3}, {%4,%5,%6,%7}, {%8,%9}, {%0,%1,%2,%3};"
          : "+f"(oc[2*np+1][0]),"+f"(oc[2*np+1][1]),"+f"(oc[2*np+1][2]),"+f"(oc[2*np+1][3])
          : "r"(a0),"r"(a1),"r"(a2),"r"(a3), "r"(b2),"r"(b3));
      }
    }
    #pragma unroll
    for (int k = 0; k < 4; k++) {
      unsigned b0,b1;
      unsigned bd = vsm_s + (eoffh + k*16*72)*2;
      asm volatile("ldmatrix.sync.aligned.m8n8.x2.trans.shared.b16 {%0,%1}, [%2];"
        : "=r"(b0),"=r"(b1) : "r"(bd));
      unsigned a0=*(unsigned*)&fa[k][0], a1=*(unsigned*)&fa[k][1];
      unsigned a2=*(unsigned*)&fa[k][2], a3=*(unsigned*)&fa[k][3];
      asm volatile(
        "mma.sync.aligned.m16n8k16.row.col.f32.f16.f16.f32 "
        "{%0,%1,%2,%3}, {%4,%5,%6,%7}, {%8,%9}, {%0,%1,%2,%3};"
        : "+f"(oce[0]),"+f"(oce[1]),"+f"(oce[2]),"+f"(oce[3])
        : "r"(a0),"r"(a1),"r"(a2),"r"(a3), "r"(b0),"r"(b1));
    }

    if (it < 15) {
      kpref(s0 + 64);
      vasync((__half*)(sm + SM_VSM + (cur^1)*9216), s0 + 64);
    }
  }

  float den_lo = __shfl_sync(0xFFFFFFFFu, oce[0], lid & 28);
  float den_hi = __shfl_sync(0xFFFFFFFFu, oce[2], lid & 28);
  const int tlo = t0 + r0, thi = t0 + r1;
  const float invlo = 1.f / (1.f + den_lo);
  const float invhi = 1.f / (1.f + den_hi);
  __half* hop = g_hoh + (size_t)bh*TT*DD;
  #pragma unroll
  for (int nt = 0; nt < 8; nt++) {
    int c = nt*8 + 2*lam;
    if (tlo < TT) {
      __half2 o = __floats2half2_rn(oc[nt][0]*invlo, oc[nt][1]*invlo);
      *(unsigned*)(hop + (size_t)tlo*DD + c) = *(unsigned*)&o;
    }
    if (thi < TT) {
      __half2 o = __floats2half2_rn(oc[nt][2]*invhi, oc[nt][3]*invhi);
      *(unsigned*)(hop + (size_t)thi*DD + c) = *(unsigned*)&o;
    }
  }
}

// K3: head-sum (fp16 in) + ReLU + Wf + residual
__global__ __launch_bounds__(256) void out_kernel(
    const float* __restrict__ x, const float* __restrict__ wf,
    float* __restrict__ out) {
  __shared__ float r[4][64];
  __shared__ float wfs[64*65];
  const int tl = threadIdx.x >> 6, w = threadIdx.x & 63;
  const int token = blockIdx.x*4 + tl, b = token / TT, t = token - b*TT;
  for (int i = threadIdx.x; i < 4160; i += 256) wfs[i] = wf[i];
  float s = 0.f;
  #pragma unroll
  for (int h = 0; h < NHH; h++)
    s += __half2float(g_hoh[((size_t)(b*NHH + h)*TT + t)*DD + w]);
  r[tl][w] = fmaxf(s, 0.f);
  __syncthreads();
  float acc = wfs[w*65 + 64];
  #pragma unroll 8
  for (int k = 0; k < 64; k++) acc += wfs[w*65 + k] * r[tl][k];
  out[(size_t)token*DD + w] = x[(size_t)token*DD + w] + acc;
}

extern "C" void kernel_launch(void* const* d_in, const int* in_sizes, int n_in,
                              void* d_out, int out_size) {
  const float* x  = (const float*)d_in[0];
  const float* wq = (const float*)d_in[1];
  const float* wv = (const float*)d_in[2];
  const float* wk = (const float*)d_in[3];
  const float* wf = (const float*)d_in[4];
  float* out = (float*)d_out;
  (void)in_sizes; (void)n_in; (void)out_size;

  cudaFuncSetAttribute(attn_kernel, cudaFuncAttributeMaxDynamicSharedMemorySize,
                       ATTN_SMEM);
  proj_kernel<<<dim3(8000/64, 512/64, 3), 256>>>(x, wq, wv, wk);
  attn_kernel<<<dim3(16, NHH, BB), 128, ATTN_SMEM>>>();
  out_kernel<<<8000/4, 256>>>(x, wf, out);
}

// round 15
// speedup vs baseline: 1.2938x; 1.1531x over previous
#include <cuda_runtime.h>
#include <cuda_fp16.h>
#include <cstdint>

#define BB  8
#define TT  1000
#define NHH 8
#define DD  64
#define SCALE_LOG2E (-0.18033688011112042f)
#define POS2SCALE   (0.36067376022224084f)

__device__ __half g_qh[BB*NHH*TT*DD];
__device__ __half g_kh[BB*NHH*TT*DD];
__device__ __half g_vh[BB*NHH*TT*DD];
__device__ __half g_k1h[BB*NHH*TT];
__device__ __half g_hoh[BB*NHH*TT*DD];

__device__ __forceinline__ unsigned smem_u32(const void* p) {
  return (unsigned)__cvta_generic_to_shared(p);
}
__device__ __forceinline__ unsigned duph_(float v) {
  __half h = __float2half_rn(v);
  unsigned u = (unsigned)*(unsigned short*)&h;
  return u | (u << 16);
}

// K0: fused projections. z=0: q (fp16x2) -> g_qh; z=1: v -> g_vh;
// z=2 (y==0): k = x*wk -> g_kh + prescaled row sums.
__global__ __launch_bounds__(256) void proj_kernel(
    const float* __restrict__ x, const float* __restrict__ wq,
    const float* __restrict__ wv, const float* __restrict__ wk) {
  __shared__ unsigned xs2[64*68];
  __shared__ unsigned ws2[64*36];
  __shared__ float    wks[512];
  const int tid = threadIdx.x;
  const int z = blockIdx.z;

  if (z == 2) {
    if (blockIdx.y) return;
    float* xs = (float*)xs2;
    const int tok0 = blockIdx.x * 64;
    for (int i = tid; i < 512; i += 256) wks[i] = wk[i];
    for (int i = tid; i < 1024; i += 256) {
      int tl = i >> 4, k4 = (i & 15) << 2;
      float4 v = *(const float4*)&x[(tok0 + tl)*DD + k4];
      xs[tl*68+k4] = v.x; xs[tl*68+k4+1] = v.y;
      xs[tl*68+k4+2] = v.z; xs[tl*68+k4+3] = v.w;
    }
    __syncthreads();
    const int h = tid >> 5, tl0 = tid & 31;
    #pragma unroll
    for (int hf = 0; hf < 2; hf++) {
      int tl = tl0 + hf*32;
      int gt = tok0 + tl, b = gt / TT, t = gt - b*TT;
      __half* dst = g_kh + ((size_t)(b*NHH + h)*TT + t)*DD;
      float sum = 0.f;
      #pragma unroll
      for (int c = 0; c < 8; c++) {
        int d = c*8;
        float p[8];
        #pragma unroll
        for (int j = 0; j < 8; j++) { p[j] = xs[tl*68+d+j]*wks[h*64+d+j]; sum += p[j]; }
        __half2 h0 = __floats2half2_rn(p[0], p[1]);
        __half2 h1 = __floats2half2_rn(p[2], p[3]);
        __half2 h2 = __floats2half2_rn(p[4], p[5]);
        __half2 h3 = __floats2half2_rn(p[6], p[7]);
        uint4 o; o.x=*(unsigned*)&h0; o.y=*(unsigned*)&h1; o.z=*(unsigned*)&h2; o.w=*(unsigned*)&h3;
        *(uint4*)(dst + d) = o;
      }
      g_k1h[(size_t)(b*NHH + h)*TT + t] = __float2half_rn(sum * SCALE_LOG2E);
    }
    return;
  }

  const float* w = z ? wv : wq;
  __half* dstg   = z ? g_vh : g_qh;
  const int m0 = blockIdx.x * 64, n0 = blockIdx.y * 64;

  for (int i = tid; i < 1024; i += 256) {
    int m = i >> 4, k4 = (i & 15) << 2;
    float4 v4 = *(const float4*)&x[(m0 + m)*DD + k4];
    xs2[(k4)*68+m]   = duph_(v4.x);
    xs2[(k4+1)*68+m] = duph_(v4.y);
    xs2[(k4+2)*68+m] = duph_(v4.z);
    xs2[(k4+3)*68+m] = duph_(v4.w);
  }
  for (int i = tid; i < 2048; i += 256) {
    int np = i >> 6, k = i & 63;
    float a = w[(n0 + 2*np)*65 + k];
    float b = w[(n0 + 2*np + 1)*65 + k];
    __half2 h = __floats2half2_rn(a, b);
    ws2[k*36 + np] = *(unsigned*)&h;
  }
  __syncthreads();

  const int tm = (tid >> 4) * 4, tn = (tid & 15) * 4, tnp = tn >> 1;
  __half2 acc2[4][2];
  #pragma unroll
  for (int i = 0; i < 4; i++) {
    acc2[i][0] = __float2half2_rn(0.f);
    acc2[i][1] = __float2half2_rn(0.f);
  }
  #pragma unroll 8
  for (int k = 0; k < 64; k++) {
    uint4 xq = *(const uint4*)&xs2[k*68 + tm];
    uint2 wp = *(const uint2*)&ws2[k*36 + tnp];
    __half2 xv[4]; *(uint4*)xv = xq;
    __half2 w0 = *(__half2*)&wp.x, w1 = *(__half2*)&wp.y;
    #pragma unroll
    for (int i = 0; i < 4; i++) {
      acc2[i][0] = __hfma2(xv[i], w0, acc2[i][0]);
      acc2[i][1] = __hfma2(xv[i], w1, acc2[i][1]);
    }
  }

  const int n = n0 + tn, h = n >> 6, d0 = n & 63;
  __half2 b01 = __floats2half2_rn(w[n*65+64],     w[(n+1)*65+64]);
  __half2 b23 = __floats2half2_rn(w[(n+2)*65+64], w[(n+3)*65+64]);
  #pragma unroll
  for (int i = 0; i < 4; i++) {
    int m = m0 + tm + i, b = m / TT, t = m - b*TT;
    __half2 o0 = __hadd2(acc2[i][0], b01);
    __half2 o1 = __hadd2(acc2[i][1], b23);
    uint2 o; o.x = *(unsigned*)&o0; o.y = *(unsigned*)&o1;
    *(uint2*)(dstg + ((size_t)(b*NHH+h)*TT + t)*DD + d0) = o;
  }
}

// K2 smem: qsh dup [64][68]u @0 (17408); ksh x2 [64][36]u @17408 (18432);
// vsm half[64][72] x2 @35840 (18432); q1 @54272 (128); k1 x2 @54400 (2*144)
#define SM_QSH   0
#define SM_KSH   17408
#define SM_VSM   35840
#define SM_Q1    54272
#define SM_K1    54400
#define ATTN_SMEM 54720

__global__ __launch_bounds__(128, 4) void attn_kernel() {
  extern __shared__ char sm[];
  unsigned* qsh  = (unsigned*)(sm + SM_QSH);
  __half*   q1sh = (__half*)(sm + SM_Q1);

  const int tid = threadIdx.x, wid = tid >> 5, lid = tid & 31;
  const int bh = blockIdx.z*NHH + blockIdx.y;
  const int t0 = blockIdx.x * 64;
  const int lam = lid & 3;
  const int r0 = wid*16 + (lid >> 2), r1 = r0 + 8;

  const __half* qhg = g_qh + (size_t)bh*TT*DD;
  const __half* khg = g_kh + (size_t)bh*TT*DD;
  const __half* vhg = g_vh + (size_t)bh*TT*DD;
  const __half* k1g = g_k1h + (size_t)bh*TT;

  for (int i = tid; i < 1024; i += 128) {
    int t = i >> 4, c4 = (i & 15) << 2;
    int tr = t0 + t; if (tr >= TT) tr = TT - 1;
    uint2 a = *(const uint2*)(qhg + (size_t)tr*DD + c4);
    qsh[(c4)*68+t]   = __byte_perm(a.x, a.x, 0x1010);
    qsh[(c4+1)*68+t] = __byte_perm(a.x, a.x, 0x3232);
    qsh[(c4+2)*68+t] = __byte_perm(a.y, a.y, 0x1010);
    qsh[(c4+3)*68+t] = __byte_perm(a.y, a.y, 0x3232);
  }
  if (tid < 64) {
    int tr = t0 + tid; if (tr >= TT) tr = TT - 1;
    const uint4* qr = (const uint4*)(qhg + (size_t)tr*DD);
    float s = 0.f;
    #pragma unroll
    for (int i = 0; i < 8; i++) {
      uint4 v = qr[i];
      __half2* hp = (__half2*)&v;
      #pragma unroll
      for (int j = 0; j < 4; j++) { float2 f = __half22float2(hp[j]); s += f.x + f.y; }
    }
    q1sh[tid] = __float2half_rn(s * SCALE_LOG2E);
  }

  uint2 ka[4], kc[4];
  unsigned k1u[4];
  auto kpref = [&](int s0) {
    #pragma unroll
    for (int i = 0; i < 4; i++) {
      int idx = tid + i*128;
      int sp = idx >> 4, c4 = (idx & 15) << 2;
      int sA = s0 + 2*sp, sB = sA + 1;
      if ((tid & 15) == 0) {
        int sE = sA; if (sE > TT - 2) sE = TT - 2;
        k1u[i] = *(const unsigned*)(k1g + sE);
      }
      if (sA >= TT) sA = TT - 1;
      if (sB >= TT) sB = TT - 1;
      ka[i] = *(const uint2*)(khg + (size_t)sA*DD + c4);
      kc[i] = *(const uint2*)(khg + (size_t)sB*DD + c4);
    }
  };
  auto kstore = [&](int buf) {
    unsigned* kb  = (unsigned*)(sm + SM_KSH + buf*9216);
    unsigned* k1b = (unsigned*)(sm + SM_K1 + buf*144);
    #pragma unroll
    for (int i = 0; i < 4; i++) {
      int idx = tid + i*128;
      int sp = idx >> 4, c4 = (idx & 15) << 2;
      int j = ((sp & 3) << 3) + (sp >> 2);
      kb[(c4)*36+j]   = __byte_perm(ka[i].x, kc[i].x, 0x5410);
      kb[(c4+1)*36+j] = __byte_perm(ka[i].x, kc[i].x, 0x7632);
      kb[(c4+2)*36+j] = __byte_perm(ka[i].y, kc[i].y, 0x5410);
      kb[(c4+3)*36+j] = __byte_perm(ka[i].y, kc[i].y, 0x7632);
      if ((tid & 15) == 0) k1b[j] = k1u[i];
    }
  };
  auto vasync = [&](int buf, int s0) {
    __half* vbuf = (__half*)(sm + SM_VSM + buf*9216);
    #pragma unroll
    for (int i = 0; i < 4; i++) {
      int idx = tid + i*128;
      int s = idx >> 3, c = idx & 7;
      int sr = s0 + s;
      bool ok = sr < TT;
      if (!ok) sr = TT - 1;
      unsigned dst = smem_u32(vbuf + s*72 + c*8);
      asm volatile("cp.async.ca.shared.global [%0], [%1], 16;"
                   :: "r"(dst), "l"(vhg + (size_t)sr*DD + c*8));
      if (c == 0) {
        uint4 one = make_uint4(ok ? 0x00003C00u : 0u, 0u, 0u, 0u);
        *(uint4*)(vbuf + s*72 + 64) = one;
      }
    }
    asm volatile("cp.async.commit_group;" ::: "memory");
  };

  kpref(0); kstore(0);          // tile 0 k into buf0 (no readers yet)
  vasync(0, 0);
  kpref(64);                    // tile 1 k in regs
  __syncthreads();              // qsh, q1sh, ksh buf0 visible
  const __half2 q1a2 = __half2half2(q1sh[r0]);
  const __half2 q1b2 = __half2half2(q1sh[r1]);

  const unsigned boffh = ((lid & 7) + ((lid >> 3) & 1)*8)*72 + ((lid >> 4) & 1)*8;
  const unsigned eoffh = ((lid & 7) + ((lid >> 3) & 1)*8)*72 + 64;
  const __half2 pos2 = __float2half2_rn(POS2SCALE);

  float oc[8][4], oce[4];
  #pragma unroll
  for (int nt = 0; nt < 8; nt++)
    #pragma unroll
    for (int r = 0; r < 4; r++) oc[nt][r] = 0.f;
  #pragma unroll
  for (int r = 0; r < 4; r++) oce[r] = 0.f;

  for (int it = 0; it < 16; it++) {
    const int s0 = it * 64;
    const int cur = it & 1, nxt = cur ^ 1;
    unsigned* kshc = (unsigned*)(sm + SM_KSH + cur*9216);
    unsigned* k1c  = (unsigned*)(sm + SM_K1 + cur*144);

    asm volatile("cp.async.wait_group 0;" ::: "memory");
    __syncthreads();   // ONLY barrier per tile: vsm(cur) + all it-1 work done

    // scores: M = sum_d min(q,k) into mma A-fragment slots
    __half2 fa[4][4];
    #pragma unroll
    for (int k = 0; k < 4; k++)
      #pragma unroll
      for (int r = 0; r < 4; r++) fa[k][r] = __float2half2_rn(0.f);

    #pragma unroll 4
    for (int d = 0; d < 64; d++) {
      unsigned qau = qsh[d*68 + r0], qbu = qsh[d*68 + r1];
      __half2 qa = *(__half2*)&qau, qb = *(__half2*)&qbu;
      __half2 kk[8];
      *(uint4*)kk     = *(const uint4*)(kshc + d*36 + lam*8);
      *(uint4*)(kk+4) = *(const uint4*)(kshc + d*36 + lam*8 + 4);
      #pragma unroll
      for (int k = 0; k < 4; k++) {
        fa[k][0] = __hadd2(fa[k][0], __hmin2(qa, kk[2*k]));
        fa[k][1] = __hadd2(fa[k][1], __hmin2(qb, kk[2*k]));
        fa[k][2] = __hadd2(fa[k][2], __hmin2(qa, kk[2*k+1]));
        fa[k][3] = __hadd2(fa[k][3], __hmin2(qb, kk[2*k+1]));
      }
    }

    // overlap next-tile k staging with exp+mma
    if (it < 15) {
      kstore(nxt);              // tile it+1 into other buffer
      kpref(s0 + 128 < TT ? s0 + 128 : 960);   // tile it+2 regs
    }

    // p = exp2(q1+k1 + pos2*M)
    #pragma unroll
    for (int k = 0; k < 4; k++) {
      unsigned k1a = k1c[lam*8 + 2*k], k1b = k1c[lam*8 + 2*k + 1];
      __half2 k1ah = *(__half2*)&k1a, k1bh = *(__half2*)&k1b;
      __half2 cc[4];
      cc[0] = __hadd2(q1a2, k1ah);
      cc[1] = __hadd2(q1b2, k1ah);
      cc[2] = __hadd2(q1a2, k1bh);
      cc[3] = __hadd2(q1b2, k1bh);
      #pragma unroll
      for (int r = 0; r < 4; r++) {
        __half2 e = __hfma2(fa[k][r], pos2, cc[r]);
        unsigned ein = *(unsigned*)&e, eout;
        asm("ex2.approx.f16x2 %0, %1;" : "=r"(eout) : "r"(ein));
        if (it == 15) {
          int c = 16*k + 2*lam + ((r >= 2) ? 8 : 0);
          if (s0 + c >= TT) eout = 0u;
        }
        fa[k][r] = *(__half2*)&eout;
      }
    }

    // AV mma + ones column
    const unsigned vsm_s = smem_u32(sm + SM_VSM + cur*9216);
    #pragma unroll
    for (int np = 0; np < 4; np++) {
      #pragma unroll
      for (int k = 0; k < 4; k++) {
        unsigned b0,b1,b2,b3;
        unsigned bd = vsm_s + (boffh + k*16*72 + np*16)*2;
        asm volatile("ldmatrix.sync.aligned.m8n8.x4.trans.shared.b16 {%0,%1,%2,%3}, [%4];"
          : "=r"(b0),"=r"(b1),"=r"(b2),"=r"(b3) : "r"(bd));
        unsigned a0=*(unsigned*)&fa[k][0], a1=*(unsigned*)&fa[k][1];
        unsigned a2=*(unsigned*)&fa[k][2], a3=*(unsigned*)&fa[k][3];
        asm volatile(
          "mma.sync.aligned.m16n8k16.row.col.f32.f16.f16.f32 "
          "{%0,%1,%2,%3}, {%4,%5,%6,%7}, {%8,%9}, {%0,%1,%2,%3};"
          : "+f"(oc[2*np][0]),"+f"(oc[2*np][1]),"+f"(oc[2*np][2]),"+f"(oc[2*np][3])
          : "r"(a0),"r"(a1),"r"(a2),"r"(a3), "r"(b0),"r"(b1));
        asm volatile(
          "mma.sync.aligned.m16n8k16.row.col.f32.f16.f16.f32 "
          "{%0,%1,%2,%3}, {%4,%5,%6,%7}, {%8,%9}, {%0,%1,%2,%3};"
          : "+f"(oc[2*np+1][0]),"+f"(oc[2*np+1][1]),"+f"(oc[2*np+1][2]),"+f"(oc[2*np+1][3])
          : "r"(a0),"r"(a1),"r"(a2),"r"(a3), "r"(b2),"r"(b3));
      }
    }
    #pragma unroll
    for (int k = 0; k < 4; k++) {
      unsigned b0,b1;
      unsigned bd = vsm_s + (eoffh + k*16*72)*2;
      asm volatile("ldmatrix.sync.aligned.m8n8.x2.trans.shared.b16 {%0,%1}, [%2];"
        : "=r"(b0),"=r"(b1) : "r"(bd));
      unsigned a0=*(unsigned*)&fa[k][0], a1=*(unsigned*)&fa[k][1];
      unsigned a2=*(unsigned*)&fa[k][2], a3=*(unsigned*)&fa[k][3];
      asm volatile(
        "mma.sync.aligned.m16n8k16.row.col.f32.f16.f16.f32 "
        "{%0,%1,%2,%3}, {%4,%5,%6,%7}, {%8,%9}, {%0,%1,%2,%3};"
        : "+f"(oce[0]),"+f"(oce[1]),"+f"(oce[2]),"+f"(oce[3])
        : "r"(a0),"r"(a1),"r"(a2),"r"(a3), "r"(b0),"r"(b1));
    }

    if (it < 15) vasync(nxt, s0 + 64);
  }

  float den_lo = __shfl_sync(0xFFFFFFFFu, oce[0], lid & 28);
  float den_hi = __shfl_sync(0xFFFFFFFFu, oce[2], lid & 28);
  const int tlo = t0 + r0, thi = t0 + r1;
  const float invlo = 1.f / (1.f + den_lo);
  const float invhi = 1.f / (1.f + den_hi);
  __half* hop = g_hoh + (size_t)bh*TT*DD;
  #pragma unroll
  for (int nt = 0; nt < 8; nt++) {
    int c = nt*8 + 2*lam;
    if (tlo < TT) {
      __half2 o = __floats2half2_rn(oc[nt][0]*invlo, oc[nt][1]*invlo);
      *(unsigned*)(hop + (size_t)tlo*DD + c) = *(unsigned*)&o;
    }
    if (thi < TT) {
      __half2 o = __floats2half2_rn(oc[nt][2]*invhi, oc[nt][3]*invhi);
      *(unsigned*)(hop + (size_t)thi*DD + c) = *(unsigned*)&o;
    }
  }
}

// K3: 16 tokens/block; wf smem fill amortized 4x
__global__ __launch_bounds__(256) void out_kernel(
    const float* __restrict__ x, const float* __restrict__ wf,
    float* __restrict__ out) {
  __shared__ float r[16][64];
  __shared__ float wfs[64*65];
  const int tl = threadIdx.x >> 6, w = threadIdx.x & 63;
  for (int i = threadIdx.x; i < 4160; i += 256) wfs[i] = wf[i];

  #pragma unroll
  for (int g = 0; g < 4; g++) {
    int token = blockIdx.x*16 + g*4 + tl;
    int b = token / TT, t = token - b*TT;
    float s = 0.f;
    #pragma unroll
    for (int h = 0; h < NHH; h++)
      s += __half2float(g_hoh[((size_t)(b*NHH + h)*TT + t)*DD + w]);
    r[g*4 + tl][w] = fmaxf(s, 0.f);
  }
  __syncthreads();

  #pragma unroll
  for (int g = 0; g < 4; g++) {
    int token = blockIdx.x*16 + g*4 + tl;
    float acc = wfs[w*65 + 64];
    #pragma unroll 8
    for (int k = 0; k < 64; k++) acc += wfs[w*65 + k] * r[g*4 + tl][k];
    out[(size_t)token*DD + w] = x[(size_t)token*DD + w] + acc;
  }
}

extern "C" void kernel_launch(void* const* d_in, const int* in_sizes, int n_in,
                              void* d_out, int out_size) {
  const float* x  = (const float*)d_in[0];
  const float* wq = (const float*)d_in[1];
  const float* wv = (const float*)d_in[2];
  const float* wk = (const float*)d_in[3];
  const float* wf = (const float*)d_in[4];
  float* out = (float*)d_out;
  (void)in_sizes; (void)n_in; (void)out_size;

  cudaFuncSetAttribute(attn_kernel, cudaFuncAttributeMaxDynamicSharedMemorySize,
                       ATTN_SMEM);
  proj_kernel<<<dim3(8000/64, 512/64, 3), 256>>>(x, wq, wv, wk);
  attn_kernel<<<dim3(16, NHH, BB), 128, ATTN_SMEM>>>();
  out_kernel<<<8000/16, 256>>>(x, wf, out);
}